// round 8
// baseline (speedup 1.0000x reference)
#include <cuda_runtime.h>

// Problem constants (B=64, D=256, H=32, W=32, K=1024)
#define TOK_N   65536   // B*H*W tokens
#define DDIM    256
#define KCODES  1024

// Tiling: 16 tx (codes) x 16 ty (tokens), TM=8 tokens, TN=16 codes per thread
#define BM      128     // tokens per block
#define BN      256     // codes per tile
#define BD      32      // d-chunk staged in smem
#define TM      8
#define TN      16
#define NTHREADS 256

#define SMEM_FLOATS (DDIM*BM + BD*BN)     // 32768 + 8192 = 40960
#define SMEM_BYTES  (SMEM_FLOATS * 4)     // 163840

// Scratch in device globals (no allocations allowed in kernel_launch)
__device__ float g_cbT[DDIM * KCODES];      // transposed codebook [d][k]
__device__ float g_cnorm_half[KCODES];      // 0.5 * ||c_k||^2

// ---------------------------------------------------------------------------
// packed f32x2 FMA (sm_100+)
// ---------------------------------------------------------------------------
__device__ __forceinline__ float2 ffma2(float2 a, float2 b, float2 c) {
    unsigned long long ua = *reinterpret_cast<unsigned long long*>(&a);
    unsigned long long ub = *reinterpret_cast<unsigned long long*>(&b);
    unsigned long long uc = *reinterpret_cast<unsigned long long*>(&c);
    unsigned long long ud;
    asm("fma.rn.f32x2 %0, %1, %2, %3;" : "=l"(ud) : "l"(ua), "l"(ub), "l"(uc));
    float2 d;
    *reinterpret_cast<unsigned long long*>(&d) = ud;
    return d;
}

// ---------------------------------------------------------------------------
// Prep: transpose codebook to [D][K] and compute 0.5*||c||^2 per code.
// ---------------------------------------------------------------------------
__global__ void __launch_bounds__(256) vq_prep(const float* __restrict__ cb) {
    int k = blockIdx.x;
    int d = threadIdx.x;
    float v = cb[k * DDIM + d];
    g_cbT[d * KCODES + k] = v;

    __shared__ float red[256];
    red[d] = v * v;
    __syncthreads();
    #pragma unroll
    for (int s = 128; s > 0; s >>= 1) {
        if (d < s) red[d] += red[d + s];
        __syncthreads();
    }
    if (d == 0) g_cnorm_half[k] = 0.5f * red[0];
}

// ---------------------------------------------------------------------------
// Main: per block, 128 tokens vs all 1024 codes.
//   score_k = dot(x, c_k) - 0.5*||c_k||^2 ;  argmax score == argmin distance.
//   NUMERICS CONTRACT (matches the R6 passing run bit-for-bit): acc starts at
//   0, fp32x2 fma over d = 0..255 with a single accumulator per (token,code),
//   then subtract 0.5||c||^2 in the epilogue. Do NOT reorder.
// ---------------------------------------------------------------------------
__global__ void __launch_bounds__(NTHREADS, 1)
vq_main(const float* __restrict__ x,
        const float* __restrict__ cb,
        float* __restrict__ out,
        int halfElems) {
    extern __shared__ float smem[];
    float* xs = smem;                 // [DDIM][BM]  128 KB
    float* cs = smem + DDIM * BM;     // [BD][BN]     32 KB (reused for reduce)

    const int tid = threadIdx.x;
    const int tx = tid & 15;          // code group (16 codes each)
    const int ty = tid >> 4;          // token group (8 tokens each)

    const int m0  = blockIdx.x * BM;  // first flat token (NHWC order)
    const int b   = m0 >> 10;         // 1024 hw positions per batch image
    const int hw0 = m0 & 1023;        // multiple of 128, run stays inside image
    const float* xbase = x + (long long)b * (DDIM * 1024) + hw0;

    // Stage x slab: xs[d][m], m contiguous -> coalesced float4 loads
    #pragma unroll
    for (int f = tid; f < DDIM * BM / 4; f += NTHREADS) {
        int d  = f >> 5;              // BM/4 = 32 float4 per d-row
        int m4 = f & 31;
        float4 v = *reinterpret_cast<const float4*>(xbase + d * 1024 + m4 * 4);
        *reinterpret_cast<float4*>(&xs[d * BM + m4 * 4]) = v;
    }

    float bestv[TM];
    int   besti[TM];
    #pragma unroll
    for (int i = 0; i < TM; i++) { bestv[i] = -1e30f; besti[i] = 0; }

    for (int t = 0; t < KCODES / BN; ++t) {
        const int n0 = t * BN;

        float2 acc[TM][TN / 2];
        #pragma unroll
        for (int i = 0; i < TM; i++)
            #pragma unroll
            for (int jp = 0; jp < TN / 2; jp++)
                acc[i][jp] = make_float2(0.f, 0.f);

        for (int d0 = 0; d0 < DDIM; d0 += BD) {
            __syncthreads();   // cs reuse guard (also orders first xs use)
            // Stage codebook chunk cs[dd][n] from pre-transposed cbT (coalesced)
            #pragma unroll
            for (int f = tid; f < BD * BN / 4; f += NTHREADS) {
                int dd = f >> 6;      // BN/4 = 64 float4 per row
                int n4 = f & 63;
                *reinterpret_cast<float4*>(&cs[dd * BN + n4 * 4]) =
                    *reinterpret_cast<const float4*>(
                        &g_cbT[(d0 + dd) * KCODES + n0 + n4 * 4]);
            }
            __syncthreads();

            #pragma unroll 4
            for (int dd = 0; dd < BD; ++dd) {
                // A fragment: 8 tokens (broadcast across tx lanes)
                float4 av0 = *reinterpret_cast<const float4*>(
                    &xs[(d0 + dd) * BM + ty * TM]);
                float4 av1 = *reinterpret_cast<const float4*>(
                    &xs[(d0 + dd) * BM + ty * TM + 4]);
                float a_[TM] = { av0.x, av0.y, av0.z, av0.w,
                                 av1.x, av1.y, av1.z, av1.w };
                // B fragment: 16 codes = 8 packed pairs
                float2 bp[TN / 2];
                #pragma unroll
                for (int q = 0; q < 4; q++) {
                    float4 bv = *reinterpret_cast<const float4*>(
                        &cs[dd * BN + tx * TN + q * 4]);
                    bp[q * 2]     = make_float2(bv.x, bv.y);
                    bp[q * 2 + 1] = make_float2(bv.z, bv.w);
                }
                #pragma unroll
                for (int i = 0; i < TM; i++) {
                    float2 pa = make_float2(a_[i], a_[i]);
                    #pragma unroll
                    for (int jp = 0; jp < TN / 2; jp++)
                        acc[i][jp] = ffma2(pa, bp[jp], acc[i][jp]);
                }
            }
        }

        // Tile epilogue: subtract 0.5||c||^2 HERE (exact R6 arithmetic), then
        // running argmax. Strict '>' keeps first/lowest index; codes visited
        // in ascending order within this thread's slots.
        #pragma unroll
        for (int jp = 0; jp < TN / 2; jp++) {
            int n = n0 + tx * TN + jp * 2;
            float c0 = g_cnorm_half[n];
            float c1 = g_cnorm_half[n + 1];
            #pragma unroll
            for (int i = 0; i < TM; i++) {
                float s0 = acc[i][jp].x - c0;
                float s1 = acc[i][jp].y - c1;
                if (s0 > bestv[i]) { bestv[i] = s0; besti[i] = n; }
                if (s1 > bestv[i]) { bestv[i] = s1; besti[i] = n + 1; }
            }
        }
    }

    // Cross-thread argmax reduce over the 16 tx lanes (tie-break -> lowest idx)
    __syncthreads();
    float* rv = cs;                                   // [BM][16]
    int*   ri = reinterpret_cast<int*>(cs + BM * 16); // [BM][16]
    #pragma unroll
    for (int i = 0; i < TM; i++) {
        int m = ty * TM + i;
        rv[m * 16 + tx] = bestv[i];
        ri[m * 16 + tx] = besti[i];
    }
    __syncthreads();
    int* fidx = reinterpret_cast<int*>(cs + 2 * BM * 16);
    if (tid < BM) {
        float bv = rv[tid * 16];
        int   bi = ri[tid * 16];
        #pragma unroll
        for (int s = 1; s < 16; s++) {
            float v  = rv[tid * 16 + s];
            int   ix = ri[tid * 16 + s];
            if (v > bv || (v == bv && ix < bi)) { bv = v; bi = ix; }
        }
        fidx[tid] = bi;
    }
    __syncthreads();

    // Gather + write both outputs. Raw reshape => out linear index = n*D + d.
    const float4* cb4 = reinterpret_cast<const float4*>(cb);
    float4* o1 = reinterpret_cast<float4*>(out);
    float4* o2 = reinterpret_cast<float4*>(out + halfElems);
    #pragma unroll
    for (int f = tid; f < BM * (DDIM / 4); f += NTHREADS) {
        int m  = f >> 6;              // DDIM/4 = 64 float4 per token
        int d4 = f & 63;
        float4 v = cb4[fidx[m] * (DDIM / 4) + d4];
        long long o = (long long)(m0 + m) * (DDIM / 4) + d4;
        o1[o] = v;
        o2[o] = v;
    }
}

// ---------------------------------------------------------------------------
extern "C" void kernel_launch(void* const* d_in, const int* in_sizes, int n_in,
                              void* d_out, int out_size) {
    const float* x  = reinterpret_cast<const float*>(d_in[0]);
    const float* cb = reinterpret_cast<const float*>(d_in[1]);
    if (n_in >= 2 && in_sizes[0] == KCODES * DDIM && in_sizes[1] != KCODES * DDIM) {
        const float* tmp = x; x = cb; cb = tmp;
    }
    float* out = reinterpret_cast<float*>(d_out);
    int halfElems = out_size / 2;     // (z_hat, z_q) concatenated; identical forward

    cudaFuncSetAttribute(vq_main, cudaFuncAttributeMaxDynamicSharedMemorySize, SMEM_BYTES);

    vq_prep<<<KCODES, 256>>>(cb);
    vq_main<<<TOK_N / BM, NTHREADS, SMEM_BYTES>>>(x, cb, out, halfElems);
}

// round 9
// speedup vs baseline: 1.0004x; 1.0004x over previous
#include <cuda_runtime.h>

// Problem constants (B=64, D=256, H=32, W=32, K=1024)
#define TOK_N   65536   // B*H*W tokens
#define DDIM    256
#define KCODES  1024

// Tiling: 16 tx (codes) x 16 ty (tokens), TM=8 tokens, TN=16 codes per thread
#define BM      128     // tokens per block
#define BN      256     // codes per tile
#define BD      32      // d-chunk staged in smem
#define TM      8
#define TN      16
#define NTHREADS 256

#define SMEM_FLOATS (DDIM*BM + BD*BN)     // 32768 + 8192 = 40960
#define SMEM_BYTES  (SMEM_FLOATS * 4)     // 163840

// Scratch in device globals (no allocations allowed in kernel_launch)
__device__ float g_cbT[DDIM * KCODES];      // transposed codebook [d][k]
__device__ float g_cnorm_half[KCODES];      // 0.5 * ||c_k||^2

// ---------------------------------------------------------------------------
// packed f32x2 FMA (sm_100+)
// ---------------------------------------------------------------------------
__device__ __forceinline__ float2 ffma2(float2 a, float2 b, float2 c) {
    unsigned long long ua = *reinterpret_cast<unsigned long long*>(&a);
    unsigned long long ub = *reinterpret_cast<unsigned long long*>(&b);
    unsigned long long uc = *reinterpret_cast<unsigned long long*>(&c);
    unsigned long long ud;
    asm("fma.rn.f32x2 %0, %1, %2, %3;" : "=l"(ud) : "l"(ua), "l"(ub), "l"(uc));
    float2 d;
    *reinterpret_cast<unsigned long long*>(&d) = ud;
    return d;
}

// ---------------------------------------------------------------------------
// Prep: transpose codebook to [D][K] and compute 0.5*||c||^2 per code.
// ---------------------------------------------------------------------------
__global__ void __launch_bounds__(256) vq_prep(const float* __restrict__ cb) {
    int k = blockIdx.x;
    int d = threadIdx.x;
    float v = cb[k * DDIM + d];
    g_cbT[d * KCODES + k] = v;

    __shared__ float red[256];
    red[d] = v * v;
    __syncthreads();
    #pragma unroll
    for (int s = 128; s > 0; s >>= 1) {
        if (d < s) red[d] += red[d + s];
        __syncthreads();
    }
    if (d == 0) g_cnorm_half[k] = 0.5f * red[0];
}

// ---------------------------------------------------------------------------
// Main: per block, 128 tokens vs all 1024 codes.
//   score_k = dot(x, c_k) - 0.5*||c_k||^2 ;  argmax score == argmin distance.
//   NUMERICS CONTRACT (matches the R6 passing run bit-for-bit): acc starts at
//   0, fp32x2 fma over d = 0..255 with a single accumulator per (token,code),
//   then subtract 0.5||c||^2 in the epilogue. Do NOT reorder.
// ---------------------------------------------------------------------------
__global__ void __launch_bounds__(NTHREADS, 1)
vq_main(const float* __restrict__ x,
        const float* __restrict__ cb,
        float* __restrict__ out,
        int halfElems) {
    extern __shared__ float smem[];
    float* xs = smem;                 // [DDIM][BM]  128 KB
    float* cs = smem + DDIM * BM;     // [BD][BN]     32 KB (reused for reduce)

    const int tid = threadIdx.x;
    const int tx = tid & 15;          // code group (16 codes each)
    const int ty = tid >> 4;          // token group (8 tokens each)

    const int m0  = blockIdx.x * BM;  // first flat token (NHWC order)
    const int b   = m0 >> 10;         // 1024 hw positions per batch image
    const int hw0 = m0 & 1023;        // multiple of 128, run stays inside image
    const float* xbase = x + (long long)b * (DDIM * 1024) + hw0;

    // Stage x slab: xs[d][m], m contiguous -> coalesced float4 loads
    #pragma unroll
    for (int f = tid; f < DDIM * BM / 4; f += NTHREADS) {
        int d  = f >> 5;              // BM/4 = 32 float4 per d-row
        int m4 = f & 31;
        float4 v = *reinterpret_cast<const float4*>(xbase + d * 1024 + m4 * 4);
        *reinterpret_cast<float4*>(&xs[d * BM + m4 * 4]) = v;
    }

    float bestv[TM];
    int   besti[TM];
    #pragma unroll
    for (int i = 0; i < TM; i++) { bestv[i] = -1e30f; besti[i] = 0; }

    for (int t = 0; t < KCODES / BN; ++t) {
        const int n0 = t * BN;

        float2 acc[TM][TN / 2];
        #pragma unroll
        for (int i = 0; i < TM; i++)
            #pragma unroll
            for (int jp = 0; jp < TN / 2; jp++)
                acc[i][jp] = make_float2(0.f, 0.f);

        for (int d0 = 0; d0 < DDIM; d0 += BD) {
            __syncthreads();   // cs reuse guard (also orders first xs use)
            // Stage codebook chunk cs[dd][n] from pre-transposed cbT (coalesced)
            #pragma unroll
            for (int f = tid; f < BD * BN / 4; f += NTHREADS) {
                int dd = f >> 6;      // BN/4 = 64 float4 per row
                int n4 = f & 63;
                *reinterpret_cast<float4*>(&cs[dd * BN + n4 * 4]) =
                    *reinterpret_cast<const float4*>(
                        &g_cbT[(d0 + dd) * KCODES + n0 + n4 * 4]);
            }
            __syncthreads();

            #pragma unroll 4
            for (int dd = 0; dd < BD; ++dd) {
                // A fragment: 8 tokens (broadcast across tx lanes)
                float4 av0 = *reinterpret_cast<const float4*>(
                    &xs[(d0 + dd) * BM + ty * TM]);
                float4 av1 = *reinterpret_cast<const float4*>(
                    &xs[(d0 + dd) * BM + ty * TM + 4]);
                float a_[TM] = { av0.x, av0.y, av0.z, av0.w,
                                 av1.x, av1.y, av1.z, av1.w };
                // B fragment: 16 codes = 8 packed pairs
                float2 bp[TN / 2];
                #pragma unroll
                for (int q = 0; q < 4; q++) {
                    float4 bv = *reinterpret_cast<const float4*>(
                        &cs[dd * BN + tx * TN + q * 4]);
                    bp[q * 2]     = make_float2(bv.x, bv.y);
                    bp[q * 2 + 1] = make_float2(bv.z, bv.w);
                }
                #pragma unroll
                for (int i = 0; i < TM; i++) {
                    float2 pa = make_float2(a_[i], a_[i]);
                    #pragma unroll
                    for (int jp = 0; jp < TN / 2; jp++)
                        acc[i][jp] = ffma2(pa, bp[jp], acc[i][jp]);
                }
            }
        }

        // Tile epilogue: subtract 0.5||c||^2 HERE (exact R6 arithmetic), then
        // running argmax. Strict '>' keeps first/lowest index; codes visited
        // in ascending order within this thread's slots.
        #pragma unroll
        for (int jp = 0; jp < TN / 2; jp++) {
            int n = n0 + tx * TN + jp * 2;
            float c0 = g_cnorm_half[n];
            float c1 = g_cnorm_half[n + 1];
            #pragma unroll
            for (int i = 0; i < TM; i++) {
                float s0 = acc[i][jp].x - c0;
                float s1 = acc[i][jp].y - c1;
                if (s0 > bestv[i]) { bestv[i] = s0; besti[i] = n; }
                if (s1 > bestv[i]) { bestv[i] = s1; besti[i] = n + 1; }
            }
        }
    }

    // Cross-thread argmax reduce over the 16 tx lanes (tie-break -> lowest idx)
    __syncthreads();
    float* rv = cs;                                   // [BM][16]
    int*   ri = reinterpret_cast<int*>(cs + BM * 16); // [BM][16]
    #pragma unroll
    for (int i = 0; i < TM; i++) {
        int m = ty * TM + i;
        rv[m * 16 + tx] = bestv[i];
        ri[m * 16 + tx] = besti[i];
    }
    __syncthreads();
    int* fidx = reinterpret_cast<int*>(cs + 2 * BM * 16);
    if (tid < BM) {
        float bv = rv[tid * 16];
        int   bi = ri[tid * 16];
        #pragma unroll
        for (int s = 1; s < 16; s++) {
            float v  = rv[tid * 16 + s];
            int   ix = ri[tid * 16 + s];
            if (v > bv || (v == bv && ix < bi)) { bv = v; bi = ix; }
        }
        fidx[tid] = bi;
    }
    __syncthreads();

    // Gather + write both outputs. Raw reshape => out linear index = n*D + d.
    const float4* cb4 = reinterpret_cast<const float4*>(cb);
    float4* o1 = reinterpret_cast<float4*>(out);
    float4* o2 = reinterpret_cast<float4*>(out + halfElems);
    #pragma unroll
    for (int f = tid; f < BM * (DDIM / 4); f += NTHREADS) {
        int m  = f >> 6;              // DDIM/4 = 64 float4 per token
        int d4 = f & 63;
        float4 v = cb4[fidx[m] * (DDIM / 4) + d4];
        long long o = (long long)(m0 + m) * (DDIM / 4) + d4;
        o1[o] = v;
        o2[o] = v;
    }
}

// ---------------------------------------------------------------------------
extern "C" void kernel_launch(void* const* d_in, const int* in_sizes, int n_in,
                              void* d_out, int out_size) {
    const float* x  = reinterpret_cast<const float*>(d_in[0]);
    const float* cb = reinterpret_cast<const float*>(d_in[1]);
    if (n_in >= 2 && in_sizes[0] == KCODES * DDIM && in_sizes[1] != KCODES * DDIM) {
        const float* tmp = x; x = cb; cb = tmp;
    }
    float* out = reinterpret_cast<float*>(d_out);
    int halfElems = out_size / 2;     // (z_hat, z_q) concatenated; identical forward

    cudaFuncSetAttribute(vq_main, cudaFuncAttributeMaxDynamicSharedMemorySize, SMEM_BYTES);

    vq_prep<<<KCODES, 256>>>(cb);
    vq_main<<<TOK_N / BM, NTHREADS, SMEM_BYTES>>>(x, cb, out, halfElems);
}

// round 10
// speedup vs baseline: 1.0004x; 1.0001x over previous
#include <cuda_runtime.h>

// Problem constants (B=64, D=256, H=32, W=32, K=1024)
#define TOK_N   65536   // B*H*W tokens
#define DDIM    256
#define KCODES  1024

// Tiling: 16 tx (codes) x 16 ty (tokens), TM=8 tokens, TN=16 codes per thread
#define BM      128     // tokens per block
#define BN      256     // codes per tile
#define BD      32      // d-chunk staged in smem
#define TM      8
#define TN      16
#define NTHREADS 256

#define SMEM_FLOATS (DDIM*BM + BD*BN)     // 32768 + 8192 = 40960
#define SMEM_BYTES  (SMEM_FLOATS * 4)     // 163840

// Scratch in device globals (no allocations allowed in kernel_launch)
__device__ float g_cbT[DDIM * KCODES];      // transposed codebook [d][k]
__device__ float g_cnorm_half[KCODES];      // 0.5 * ||c_k||^2

// ---------------------------------------------------------------------------
// packed f32x2 FMA (sm_100+)
// ---------------------------------------------------------------------------
__device__ __forceinline__ float2 ffma2(float2 a, float2 b, float2 c) {
    unsigned long long ua = *reinterpret_cast<unsigned long long*>(&a);
    unsigned long long ub = *reinterpret_cast<unsigned long long*>(&b);
    unsigned long long uc = *reinterpret_cast<unsigned long long*>(&c);
    unsigned long long ud;
    asm("fma.rn.f32x2 %0, %1, %2, %3;" : "=l"(ud) : "l"(ua), "l"(ub), "l"(uc));
    float2 d;
    *reinterpret_cast<unsigned long long*>(&d) = ud;
    return d;
}

// ---------------------------------------------------------------------------
// Prep: transpose codebook to [D][K] and compute 0.5*||c||^2 per code.
// ---------------------------------------------------------------------------
__global__ void __launch_bounds__(256) vq_prep(const float* __restrict__ cb) {
    int k = blockIdx.x;
    int d = threadIdx.x;
    float v = cb[k * DDIM + d];
    g_cbT[d * KCODES + k] = v;

    __shared__ float red[256];
    red[d] = v * v;
    __syncthreads();
    #pragma unroll
    for (int s = 128; s > 0; s >>= 1) {
        if (d < s) red[d] += red[d + s];
        __syncthreads();
    }
    if (d == 0) g_cnorm_half[k] = 0.5f * red[0];
}

// ---------------------------------------------------------------------------
// Main: per block, 128 tokens vs all 1024 codes.
//   score_k = dot(x, c_k) - 0.5*||c_k||^2 ;  argmax score == argmin distance.
//   NUMERICS CONTRACT (matches the R6 passing run bit-for-bit): acc starts at
//   0, fp32x2 fma over d = 0..255 with a single accumulator per (token,code),
//   then subtract 0.5||c||^2 in the epilogue. Do NOT reorder.
// ---------------------------------------------------------------------------
__global__ void __launch_bounds__(NTHREADS, 1)
vq_main(const float* __restrict__ x,
        const float* __restrict__ cb,
        float* __restrict__ out,
        int halfElems) {
    extern __shared__ float smem[];
    float* xs = smem;                 // [DDIM][BM]  128 KB
    float* cs = smem + DDIM * BM;     // [BD][BN]     32 KB (reused for reduce)

    const int tid = threadIdx.x;
    const int tx = tid & 15;          // code group (16 codes each)
    const int ty = tid >> 4;          // token group (8 tokens each)

    const int m0  = blockIdx.x * BM;  // first flat token (NHWC order)
    const int b   = m0 >> 10;         // 1024 hw positions per batch image
    const int hw0 = m0 & 1023;        // multiple of 128, run stays inside image
    const float* xbase = x + (long long)b * (DDIM * 1024) + hw0;

    // Stage x slab: xs[d][m], m contiguous -> coalesced float4 loads
    #pragma unroll
    for (int f = tid; f < DDIM * BM / 4; f += NTHREADS) {
        int d  = f >> 5;              // BM/4 = 32 float4 per d-row
        int m4 = f & 31;
        float4 v = *reinterpret_cast<const float4*>(xbase + d * 1024 + m4 * 4);
        *reinterpret_cast<float4*>(&xs[d * BM + m4 * 4]) = v;
    }

    float bestv[TM];
    int   besti[TM];
    #pragma unroll
    for (int i = 0; i < TM; i++) { bestv[i] = -1e30f; besti[i] = 0; }

    for (int t = 0; t < KCODES / BN; ++t) {
        const int n0 = t * BN;

        float2 acc[TM][TN / 2];
        #pragma unroll
        for (int i = 0; i < TM; i++)
            #pragma unroll
            for (int jp = 0; jp < TN / 2; jp++)
                acc[i][jp] = make_float2(0.f, 0.f);

        for (int d0 = 0; d0 < DDIM; d0 += BD) {
            __syncthreads();   // cs reuse guard (also orders first xs use)
            // Stage codebook chunk cs[dd][n] from pre-transposed cbT (coalesced)
            #pragma unroll
            for (int f = tid; f < BD * BN / 4; f += NTHREADS) {
                int dd = f >> 6;      // BN/4 = 64 float4 per row
                int n4 = f & 63;
                *reinterpret_cast<float4*>(&cs[dd * BN + n4 * 4]) =
                    *reinterpret_cast<const float4*>(
                        &g_cbT[(d0 + dd) * KCODES + n0 + n4 * 4]);
            }
            __syncthreads();

            #pragma unroll 4
            for (int dd = 0; dd < BD; ++dd) {
                // A fragment: 8 tokens (broadcast across tx lanes)
                float4 av0 = *reinterpret_cast<const float4*>(
                    &xs[(d0 + dd) * BM + ty * TM]);
                float4 av1 = *reinterpret_cast<const float4*>(
                    &xs[(d0 + dd) * BM + ty * TM + 4]);
                float a_[TM] = { av0.x, av0.y, av0.z, av0.w,
                                 av1.x, av1.y, av1.z, av1.w };
                // B fragment: 16 codes = 8 packed pairs
                float2 bp[TN / 2];
                #pragma unroll
                for (int q = 0; q < 4; q++) {
                    float4 bv = *reinterpret_cast<const float4*>(
                        &cs[dd * BN + tx * TN + q * 4]);
                    bp[q * 2]     = make_float2(bv.x, bv.y);
                    bp[q * 2 + 1] = make_float2(bv.z, bv.w);
                }
                #pragma unroll
                for (int i = 0; i < TM; i++) {
                    float2 pa = make_float2(a_[i], a_[i]);
                    #pragma unroll
                    for (int jp = 0; jp < TN / 2; jp++)
                        acc[i][jp] = ffma2(pa, bp[jp], acc[i][jp]);
                }
            }
        }

        // Tile epilogue: subtract 0.5||c||^2 HERE (exact R6 arithmetic), then
        // running argmax. Strict '>' keeps first/lowest index; codes visited
        // in ascending order within this thread's slots.
        #pragma unroll
        for (int jp = 0; jp < TN / 2; jp++) {
            int n = n0 + tx * TN + jp * 2;
            float c0 = g_cnorm_half[n];
            float c1 = g_cnorm_half[n + 1];
            #pragma unroll
            for (int i = 0; i < TM; i++) {
                float s0 = acc[i][jp].x - c0;
                float s1 = acc[i][jp].y - c1;
                if (s0 > bestv[i]) { bestv[i] = s0; besti[i] = n; }
                if (s1 > bestv[i]) { bestv[i] = s1; besti[i] = n + 1; }
            }
        }
    }

    // Cross-thread argmax reduce over the 16 tx lanes (tie-break -> lowest idx)
    __syncthreads();
    float* rv = cs;                                   // [BM][16]
    int*   ri = reinterpret_cast<int*>(cs + BM * 16); // [BM][16]
    #pragma unroll
    for (int i = 0; i < TM; i++) {
        int m = ty * TM + i;
        rv[m * 16 + tx] = bestv[i];
        ri[m * 16 + tx] = besti[i];
    }
    __syncthreads();
    int* fidx = reinterpret_cast<int*>(cs + 2 * BM * 16);
    if (tid < BM) {
        float bv = rv[tid * 16];
        int   bi = ri[tid * 16];
        #pragma unroll
        for (int s = 1; s < 16; s++) {
            float v  = rv[tid * 16 + s];
            int   ix = ri[tid * 16 + s];
            if (v > bv || (v == bv && ix < bi)) { bv = v; bi = ix; }
        }
        fidx[tid] = bi;
    }
    __syncthreads();

    // Gather + write both outputs. Raw reshape => out linear index = n*D + d.
    const float4* cb4 = reinterpret_cast<const float4*>(cb);
    float4* o1 = reinterpret_cast<float4*>(out);
    float4* o2 = reinterpret_cast<float4*>(out + halfElems);
    #pragma unroll
    for (int f = tid; f < BM * (DDIM / 4); f += NTHREADS) {
        int m  = f >> 6;              // DDIM/4 = 64 float4 per token
        int d4 = f & 63;
        float4 v = cb4[fidx[m] * (DDIM / 4) + d4];
        long long o = (long long)(m0 + m) * (DDIM / 4) + d4;
        o1[o] = v;
        o2[o] = v;
    }
}

// ---------------------------------------------------------------------------
extern "C" void kernel_launch(void* const* d_in, const int* in_sizes, int n_in,
                              void* d_out, int out_size) {
    const float* x  = reinterpret_cast<const float*>(d_in[0]);
    const float* cb = reinterpret_cast<const float*>(d_in[1]);
    if (n_in >= 2 && in_sizes[0] == KCODES * DDIM && in_sizes[1] != KCODES * DDIM) {
        const float* tmp = x; x = cb; cb = tmp;
    }
    float* out = reinterpret_cast<float*>(d_out);
    int halfElems = out_size / 2;     // (z_hat, z_q) concatenated; identical forward

    cudaFuncSetAttribute(vq_main, cudaFuncAttributeMaxDynamicSharedMemorySize, SMEM_BYTES);

    vq_prep<<<KCODES, 256>>>(cb);
    vq_main<<<TOK_N / BM, NTHREADS, SMEM_BYTES>>>(x, cb, out, halfElems);
}

// round 11
// speedup vs baseline: 1.8079x; 1.8071x over previous
#include <cuda_runtime.h>
#include <cstdint>

// Problem constants (B=64, D=256, H=32, W=32, K=1024)
#define TOK_N   65536
#define DDIM    256
#define KCODES  1024

// Tiling: 16 tx (codes) x 16 ty (tokens); TM=8 tokens, TN=16 codes per thread.
// Code assignment is INTERLEAVED: thread tx owns codes {q*64 + tx*4 + j},
// q=0..3, j=0..3  -> every B LDS.128 has 16B stride across tx = conflict-free.
#define BM      128
#define BN      256
#define BD      32
#define TM      8
#define TN      16
#define NTHREADS 256
#define NCHUNK  32            // (KCODES/BN) tiles * (DDIM/BD) d-chunks

#define XS_FLOATS (DDIM*BM)          // 32768 (128 KB)
#define CS_FLOATS (BD*BN)            // 8192  (32 KB per buffer)
#define SMEM_BYTES ((XS_FLOATS + 2*CS_FLOATS) * 4)   // 192 KB

// Scratch in device globals (no allocations allowed in kernel_launch)
__device__ float g_cbT[DDIM * KCODES];      // transposed codebook [d][k]
__device__ float g_cnorm_half[KCODES];      // 0.5 * ||c_k||^2

// ---------------------------------------------------------------------------
__device__ __forceinline__ float2 ffma2(float2 a, float2 b, float2 c) {
    unsigned long long ua = *reinterpret_cast<unsigned long long*>(&a);
    unsigned long long ub = *reinterpret_cast<unsigned long long*>(&b);
    unsigned long long uc = *reinterpret_cast<unsigned long long*>(&c);
    unsigned long long ud;
    asm("fma.rn.f32x2 %0, %1, %2, %3;" : "=l"(ud) : "l"(ua), "l"(ub), "l"(uc));
    float2 d;
    *reinterpret_cast<unsigned long long*>(&d) = ud;
    return d;
}

__device__ __forceinline__ void cp_async16(uint32_t saddr, const float* gptr) {
    asm volatile("cp.async.cg.shared.global [%0], [%1], 16;"
                 :: "r"(saddr), "l"(gptr));
}
#define CP_COMMIT() asm volatile("cp.async.commit_group;" ::: "memory")
#define CP_WAIT_ALL() asm volatile("cp.async.wait_group 0;" ::: "memory")

// ---------------------------------------------------------------------------
// Prep: transpose codebook to [D][K] and compute 0.5*||c||^2 per code.
// ---------------------------------------------------------------------------
__global__ void __launch_bounds__(256) vq_prep(const float* __restrict__ cb) {
    int k = blockIdx.x;
    int d = threadIdx.x;
    float v = cb[k * DDIM + d];
    g_cbT[d * KCODES + k] = v;

    __shared__ float red[256];
    red[d] = v * v;
    __syncthreads();
    #pragma unroll
    for (int s = 128; s > 0; s >>= 1) {
        if (d < s) red[d] += red[d + s];
        __syncthreads();
    }
    if (d == 0) g_cnorm_half[k] = 0.5f * red[0];
}

// ---------------------------------------------------------------------------
// Main: per block, 128 tokens vs all 1024 codes.
//   NUMERICS CONTRACT (bit-identical to the R6 passing run): acc starts at 0,
//   packed fp32 fma over d = 0..255 with a single accumulator per
//   (token, code), subtract 0.5||c||^2 in the epilogue. Do NOT reorder.
// ---------------------------------------------------------------------------
__global__ void __launch_bounds__(NTHREADS, 1)
vq_main(const float* __restrict__ x,
        const float* __restrict__ cb,
        float* __restrict__ out,
        int halfElems) {
    extern __shared__ float smem[];
    float* xs = smem;                     // [DDIM][BM]
    float* cs = smem + XS_FLOATS;         // 2 x [BD][BN] (buf0 reused for reduce)

    const int tid = threadIdx.x;
    const int tx = tid & 15;
    const int ty = tid >> 4;

    const uint32_t xs_u = (uint32_t)__cvta_generic_to_shared(xs);
    const uint32_t cs_u = (uint32_t)__cvta_generic_to_shared(cs);

    const int m0  = blockIdx.x * BM;      // first flat token (NHWC order)
    const int b   = m0 >> 10;
    const int hw0 = m0 & 1023;            // multiple of 128
    const float* xbase = x + (long long)b * (DDIM * 1024) + hw0;

    // ---- issue x-slab loads (no data registers: cp.async) ----
    #pragma unroll 8
    for (int f = tid; f < XS_FLOATS / 4; f += NTHREADS) {
        int d  = f >> 5;                  // BM/4 = 32 float4 per d-row
        int m4 = f & 31;
        cp_async16(xs_u + (uint32_t)(d * BM + m4 * 4) * 4,
                   xbase + d * 1024 + m4 * 4);
    }
    CP_COMMIT();

    // ---- issue chunk 0 (tile 0, d0=0) into buffer 0 ----
    #pragma unroll
    for (int f = tid; f < CS_FLOATS / 4; f += NTHREADS) {
        int dd = f >> 6;                  // BN/4 = 64 float4 per row
        int n4 = f & 63;
        cp_async16(cs_u + (uint32_t)(dd * BN + n4 * 4) * 4,
                   &g_cbT[dd * KCODES + n4 * 4]);
    }
    CP_COMMIT();

    float bestv[TM];
    int   besti[TM];
    #pragma unroll
    for (int i = 0; i < TM; i++) { bestv[i] = -1e30f; besti[i] = 0; }

    float2 acc[TM][TN / 2];

    for (int c = 0; c < NCHUNK; ++c) {
        CP_WAIT_ALL();        // chunk c (and xs when c==0) landed for this thread
        __syncthreads();      // ...for all threads; also: all reads of the
                              // other buffer (compute c-1) are complete.

        // Prefetch chunk c+1 into the other buffer (overlaps compute below)
        if (c + 1 < NCHUNK) {
            const int tn = c + 1;
            const int n0n = (tn >> 3) * BN;
            const int d0n = (tn & 7) * BD;
            const uint32_t dst = cs_u + (uint32_t)((tn & 1) * CS_FLOATS) * 4;
            #pragma unroll
            for (int f = tid; f < CS_FLOATS / 4; f += NTHREADS) {
                int dd = f >> 6;
                int n4 = f & 63;
                cp_async16(dst + (uint32_t)(dd * BN + n4 * 4) * 4,
                           &g_cbT[(d0n + dd) * KCODES + n0n + n4 * 4]);
            }
            CP_COMMIT();
        }

        const float* cb_s = cs + (c & 1) * CS_FLOATS;
        const int d0 = (c & 7) * BD;

        if ((c & 7) == 0) {
            #pragma unroll
            for (int i = 0; i < TM; i++)
                #pragma unroll
                for (int jp = 0; jp < TN / 2; jp++)
                    acc[i][jp] = make_float2(0.f, 0.f);
        }

        #pragma unroll 2
        for (int dd = 0; dd < BD; ++dd) {
            // A fragment: 8 tokens (broadcast across the 16 tx lanes)
            float4 av0 = *reinterpret_cast<const float4*>(
                &xs[(d0 + dd) * BM + ty * TM]);
            float4 av1 = *reinterpret_cast<const float4*>(
                &xs[(d0 + dd) * BM + ty * TM + 4]);
            float a_[TM] = { av0.x, av0.y, av0.z, av0.w,
                             av1.x, av1.y, av1.z, av1.w };
            // B fragment: interleaved codes q*64 + tx*4 (+0..3)
            // -> per LDS.128, tx stride = 16 B: conflict-free
            float2 bp[TN / 2];
            #pragma unroll
            for (int q = 0; q < 4; q++) {
                float4 bv = *reinterpret_cast<const float4*>(
                    &cb_s[dd * BN + q * 64 + tx * 4]);
                bp[q * 2]     = make_float2(bv.x, bv.y);
                bp[q * 2 + 1] = make_float2(bv.z, bv.w);
            }
            #pragma unroll
            for (int i = 0; i < TM; i++) {
                float2 pa = make_float2(a_[i], a_[i]);
                #pragma unroll
                for (int jp = 0; jp < TN / 2; jp++)
                    acc[i][jp] = ffma2(pa, bp[jp], acc[i][jp]);
            }
        }

        // Tile epilogue: subtract 0.5||c||^2 HERE (R6 arithmetic), running
        // argmax. Within-thread visit order is ascending n (q ascending),
        // so strict '>' keeps the lowest index on exact ties.
        if ((c & 7) == 7) {
            const int n0 = (c >> 3) * BN;
            #pragma unroll
            for (int q = 0; q < 4; q++) {
                const int n = n0 + q * 64 + tx * 4;
                float4 cn = *reinterpret_cast<const float4*>(&g_cnorm_half[n]);
                const float cn_[4] = { cn.x, cn.y, cn.z, cn.w };
                #pragma unroll
                for (int j2 = 0; j2 < 2; j2++) {
                    #pragma unroll
                    for (int i = 0; i < TM; i++) {
                        float s0 = acc[i][q * 2 + j2].x - cn_[j2 * 2];
                        float s1 = acc[i][q * 2 + j2].y - cn_[j2 * 2 + 1];
                        if (s0 > bestv[i]) { bestv[i] = s0; besti[i] = n + j2 * 2; }
                        if (s1 > bestv[i]) { bestv[i] = s1; besti[i] = n + j2 * 2 + 1; }
                    }
                }
            }
        }
    }

    // Cross-thread argmax reduce over the 16 tx lanes (tie-break -> lowest idx)
    __syncthreads();
    float* rv = cs;                                   // [BM][16]
    int*   ri = reinterpret_cast<int*>(cs + BM * 16); // [BM][16]
    #pragma unroll
    for (int i = 0; i < TM; i++) {
        int m = ty * TM + i;
        rv[m * 16 + tx] = bestv[i];
        ri[m * 16 + tx] = besti[i];
    }
    __syncthreads();
    int* fidx = reinterpret_cast<int*>(cs + 2 * BM * 16);
    if (tid < BM) {
        float bv = rv[tid * 16];
        int   bi = ri[tid * 16];
        #pragma unroll
        for (int s = 1; s < 16; s++) {
            float v  = rv[tid * 16 + s];
            int   ix = ri[tid * 16 + s];
            if (v > bv || (v == bv && ix < bi)) { bv = v; bi = ix; }
        }
        fidx[tid] = bi;
    }
    __syncthreads();

    // Gather + write both outputs. Raw reshape => out linear index = n*D + d.
    const float4* cb4 = reinterpret_cast<const float4*>(cb);
    float4* o1 = reinterpret_cast<float4*>(out);
    float4* o2 = reinterpret_cast<float4*>(out + halfElems);
    #pragma unroll 4
    for (int f = tid; f < BM * (DDIM / 4); f += NTHREADS) {
        int m  = f >> 6;              // DDIM/4 = 64 float4 per token
        int d4 = f & 63;
        float4 v = cb4[fidx[m] * (DDIM / 4) + d4];
        long long o = (long long)(m0 + m) * (DDIM / 4) + d4;
        o1[o] = v;
        o2[o] = v;
    }
}

// ---------------------------------------------------------------------------
extern "C" void kernel_launch(void* const* d_in, const int* in_sizes, int n_in,
                              void* d_out, int out_size) {
    const float* x  = reinterpret_cast<const float*>(d_in[0]);
    const float* cb = reinterpret_cast<const float*>(d_in[1]);
    if (n_in >= 2 && in_sizes[0] == KCODES * DDIM && in_sizes[1] != KCODES * DDIM) {
        const float* tmp = x; x = cb; cb = tmp;
    }
    float* out = reinterpret_cast<float*>(d_out);
    int halfElems = out_size / 2;     // (z_hat, z_q) concatenated; identical forward

    cudaFuncSetAttribute(vq_main, cudaFuncAttributeMaxDynamicSharedMemorySize, SMEM_BYTES);

    vq_prep<<<KCODES, 256>>>(cb);
    vq_main<<<TOK_N / BM, NTHREADS, SMEM_BYTES>>>(x, cb, out, halfElems);
}

// round 12
// speedup vs baseline: 1.8130x; 1.0028x over previous
#include <cuda_runtime.h>
#include <cstdint>

// Problem constants (B=64, D=256, H=32, W=32, K=1024)
#define TOK_N   65536
#define DDIM    256
#define KCODES  1024

// Tiling: 32 tx (codes) x 16 ty (tokens); TM=8 tokens, TN=8 codes per thread.
// 512 threads = 16 warps = 4 warps/SMSP (double R11's latency coverage).
// Code assignment INTERLEAVED: thread tx owns codes {q*128 + tx*4 + j},
// q=0..1, j=0..3 -> every B LDS.128 is 32 lanes x 16B linear = conflict-free.
// A fragment address is warp-uniform (ty const per warp) -> LDS broadcast.
#define BM      128
#define BN      256
#define BD      32
#define TM      8
#define TN      8
#define NTHREADS 512
#define NCHUNK  32            // (KCODES/BN) tiles * (DDIM/BD) d-chunks

#define XS_FLOATS (DDIM*BM)          // 32768 (128 KB)
#define CS_FLOATS (BD*BN)            // 8192  (32 KB per buffer)
#define SMEM_BYTES ((XS_FLOATS + 2*CS_FLOATS) * 4)   // 192 KB

// Scratch in device globals (no allocations allowed in kernel_launch)
__device__ float g_cbT[DDIM * KCODES];      // transposed codebook [d][k]
__device__ float g_cnorm_half[KCODES];      // 0.5 * ||c_k||^2

// ---------------------------------------------------------------------------
__device__ __forceinline__ float2 ffma2(float2 a, float2 b, float2 c) {
    unsigned long long ua = *reinterpret_cast<unsigned long long*>(&a);
    unsigned long long ub = *reinterpret_cast<unsigned long long*>(&b);
    unsigned long long uc = *reinterpret_cast<unsigned long long*>(&c);
    unsigned long long ud;
    asm("fma.rn.f32x2 %0, %1, %2, %3;" : "=l"(ud) : "l"(ua), "l"(ub), "l"(uc));
    float2 d;
    *reinterpret_cast<unsigned long long*>(&d) = ud;
    return d;
}

__device__ __forceinline__ void cp_async16(uint32_t saddr, const float* gptr) {
    asm volatile("cp.async.cg.shared.global [%0], [%1], 16;"
                 :: "r"(saddr), "l"(gptr));
}
#define CP_COMMIT() asm volatile("cp.async.commit_group;" ::: "memory")
#define CP_WAIT_ALL() asm volatile("cp.async.wait_group 0;" ::: "memory")

// ---------------------------------------------------------------------------
// Prep: transpose codebook to [D][K] and compute 0.5*||c||^2 per code.
// ---------------------------------------------------------------------------
__global__ void __launch_bounds__(256) vq_prep(const float* __restrict__ cb) {
    int k = blockIdx.x;
    int d = threadIdx.x;
    float v = cb[k * DDIM + d];
    g_cbT[d * KCODES + k] = v;

    __shared__ float red[256];
    red[d] = v * v;
    __syncthreads();
    #pragma unroll
    for (int s = 128; s > 0; s >>= 1) {
        if (d < s) red[d] += red[d + s];
        __syncthreads();
    }
    if (d == 0) g_cnorm_half[k] = 0.5f * red[0];
}

// ---------------------------------------------------------------------------
// Main: per block, 128 tokens vs all 1024 codes.
//   NUMERICS CONTRACT (bit-identical to the R6/R11 passing runs): acc starts
//   at 0, fp32 fma over d = 0..255 sequentially with a single accumulator per
//   (token, code), subtract 0.5||c||^2 in the epilogue. Do NOT reorder.
// ---------------------------------------------------------------------------
__global__ void __launch_bounds__(NTHREADS, 1)
vq_main(const float* __restrict__ x,
        const float* __restrict__ cb,
        float* __restrict__ out,
        int halfElems) {
    extern __shared__ float smem[];
    float* xs = smem;                     // [DDIM][BM]
    float* cs = smem + XS_FLOATS;         // 2 x [BD][BN] (buf0 reused for reduce)

    const int tid = threadIdx.x;
    const int tx = tid & 31;              // code lane (8 codes each)
    const int ty = tid >> 5;              // token group (8 tokens each)

    const uint32_t xs_u = (uint32_t)__cvta_generic_to_shared(xs);
    const uint32_t cs_u = (uint32_t)__cvta_generic_to_shared(cs);

    const int m0  = blockIdx.x * BM;      // first flat token (NHWC order)
    const int b   = m0 >> 10;
    const int hw0 = m0 & 1023;            // multiple of 128
    const float* xbase = x + (long long)b * (DDIM * 1024) + hw0;

    // ---- issue x-slab loads (no data registers: cp.async) ----
    #pragma unroll 4
    for (int f = tid; f < XS_FLOATS / 4; f += NTHREADS) {
        int d  = f >> 5;                  // BM/4 = 32 float4 per d-row
        int m4 = f & 31;
        cp_async16(xs_u + (uint32_t)(d * BM + m4 * 4) * 4,
                   xbase + d * 1024 + m4 * 4);
    }
    CP_COMMIT();

    // ---- issue chunk 0 (tile 0, d0=0) into buffer 0 ----
    #pragma unroll
    for (int f = tid; f < CS_FLOATS / 4; f += NTHREADS) {
        int dd = f >> 6;                  // BN/4 = 64 float4 per row
        int n4 = f & 63;
        cp_async16(cs_u + (uint32_t)(dd * BN + n4 * 4) * 4,
                   &g_cbT[dd * KCODES + n4 * 4]);
    }
    CP_COMMIT();

    float bestv[TM];
    int   besti[TM];
    #pragma unroll
    for (int i = 0; i < TM; i++) { bestv[i] = -1e30f; besti[i] = 0; }

    float2 acc[TM][TN / 2];               // 64 scalar accumulators

    for (int c = 0; c < NCHUNK; ++c) {
        CP_WAIT_ALL();        // chunk c (and xs when c==0) landed
        __syncthreads();      // all threads; also: reads of the other buffer
                              // (compute of c-1) are complete.

        // Prefetch chunk c+1 into the other buffer (overlaps compute below)
        if (c + 1 < NCHUNK) {
            const int tn = c + 1;
            const int n0n = (tn >> 3) * BN;
            const int d0n = (tn & 7) * BD;
            const uint32_t dst = cs_u + (uint32_t)((tn & 1) * CS_FLOATS) * 4;
            #pragma unroll
            for (int f = tid; f < CS_FLOATS / 4; f += NTHREADS) {
                int dd = f >> 6;
                int n4 = f & 63;
                cp_async16(dst + (uint32_t)(dd * BN + n4 * 4) * 4,
                           &g_cbT[(d0n + dd) * KCODES + n0n + n4 * 4]);
            }
            CP_COMMIT();
        }

        const float* cb_s = cs + (c & 1) * CS_FLOATS;
        const int d0 = (c & 7) * BD;

        if ((c & 7) == 0) {
            #pragma unroll
            for (int i = 0; i < TM; i++)
                #pragma unroll
                for (int jp = 0; jp < TN / 2; jp++)
                    acc[i][jp] = make_float2(0.f, 0.f);
        }

        #pragma unroll 4
        for (int dd = 0; dd < BD; ++dd) {
            // A fragment: 8 tokens; address warp-uniform -> smem broadcast
            float4 av0 = *reinterpret_cast<const float4*>(
                &xs[(d0 + dd) * BM + ty * TM]);
            float4 av1 = *reinterpret_cast<const float4*>(
                &xs[(d0 + dd) * BM + ty * TM + 4]);
            float a_[TM] = { av0.x, av0.y, av0.z, av0.w,
                             av1.x, av1.y, av1.z, av1.w };
            // B fragment: codes q*128 + tx*4 (+0..3); 32 lanes x 16B linear
            float2 bp[TN / 2];
            #pragma unroll
            for (int q = 0; q < 2; q++) {
                float4 bv = *reinterpret_cast<const float4*>(
                    &cb_s[dd * BN + q * 128 + tx * 4]);
                bp[q * 2]     = make_float2(bv.x, bv.y);
                bp[q * 2 + 1] = make_float2(bv.z, bv.w);
            }
            #pragma unroll
            for (int i = 0; i < TM; i++) {
                float2 pa = make_float2(a_[i], a_[i]);
                #pragma unroll
                for (int jp = 0; jp < TN / 2; jp++)
                    acc[i][jp] = ffma2(pa, bp[jp], acc[i][jp]);
            }
        }

        // Tile epilogue: subtract 0.5||c||^2 HERE (exact contract arithmetic),
        // running argmax. Within-thread visit order ascending n (q, then j),
        // strict '>' keeps lowest index on exact ties.
        if ((c & 7) == 7) {
            const int n0 = (c >> 3) * BN;
            #pragma unroll
            for (int q = 0; q < 2; q++) {
                const int n = n0 + q * 128 + tx * 4;
                float4 cn = *reinterpret_cast<const float4*>(&g_cnorm_half[n]);
                const float cn_[4] = { cn.x, cn.y, cn.z, cn.w };
                #pragma unroll
                for (int j2 = 0; j2 < 2; j2++) {
                    #pragma unroll
                    for (int i = 0; i < TM; i++) {
                        float s0 = acc[i][q * 2 + j2].x - cn_[j2 * 2];
                        float s1 = acc[i][q * 2 + j2].y - cn_[j2 * 2 + 1];
                        if (s0 > bestv[i]) { bestv[i] = s0; besti[i] = n + j2 * 2; }
                        if (s1 > bestv[i]) { bestv[i] = s1; besti[i] = n + j2 * 2 + 1; }
                    }
                }
            }
        }
    }

    // Cross-thread argmax reduce over the 32 tx lanes (tie-break -> lowest idx)
    __syncthreads();
    float* rv = cs;                                   // [BM][32]
    int*   ri = reinterpret_cast<int*>(cs + BM * 32); // [BM][32]
    #pragma unroll
    for (int i = 0; i < TM; i++) {
        int m = ty * TM + i;
        rv[m * 32 + tx] = bestv[i];
        ri[m * 32 + tx] = besti[i];
    }
    __syncthreads();
    int* fidx = reinterpret_cast<int*>(cs + 2 * BM * 32);
    if (tid < BM) {
        float bv = rv[tid * 32];
        int   bi = ri[tid * 32];
        #pragma unroll
        for (int s = 1; s < 32; s++) {
            float v  = rv[tid * 32 + s];
            int   ix = ri[tid * 32 + s];
            if (v > bv || (v == bv && ix < bi)) { bv = v; bi = ix; }
        }
        fidx[tid] = bi;
    }
    __syncthreads();

    // Gather + write both outputs. Raw reshape => out linear index = n*D + d.
    const float4* cb4 = reinterpret_cast<const float4*>(cb);
    float4* o1 = reinterpret_cast<float4*>(out);
    float4* o2 = reinterpret_cast<float4*>(out + halfElems);
    #pragma unroll 4
    for (int f = tid; f < BM * (DDIM / 4); f += NTHREADS) {
        int m  = f >> 6;              // DDIM/4 = 64 float4 per token
        int d4 = f & 63;
        float4 v = cb4[fidx[m] * (DDIM / 4) + d4];
        long long o = (long long)(m0 + m) * (DDIM / 4) + d4;
        o1[o] = v;
        o2[o] = v;
    }
}

// ---------------------------------------------------------------------------
extern "C" void kernel_launch(void* const* d_in, const int* in_sizes, int n_in,
                              void* d_out, int out_size) {
    const float* x  = reinterpret_cast<const float*>(d_in[0]);
    const float* cb = reinterpret_cast<const float*>(d_in[1]);
    if (n_in >= 2 && in_sizes[0] == KCODES * DDIM && in_sizes[1] != KCODES * DDIM) {
        const float* tmp = x; x = cb; cb = tmp;
    }
    float* out = reinterpret_cast<float*>(d_out);
    int halfElems = out_size / 2;     // (z_hat, z_q) concatenated; identical forward

    cudaFuncSetAttribute(vq_main, cudaFuncAttributeMaxDynamicSharedMemorySize, SMEM_BYTES);

    vq_prep<<<KCODES, 256>>>(cb);
    vq_main<<<TOK_N / BM, NTHREADS, SMEM_BYTES>>>(x, cb, out, halfElems);
}